// round 15
// baseline (speedup 1.0000x reference)
#include <cuda_runtime.h>
#include <cstdint>

// ============================================================================
// CrossAttMultiplexer — FINAL: analytic collapse + 256-bit memory ops
//
//   q[n,i,:] = x[n,i]*WQ[0,:]; k[n,j,:] = s[n,j]*WK[0,:]
//   scores[n,i,j] = (WQ.WK)/sqrt(d) * x[n,i] * s[n,j]   (rank-1)
//   alpha = softmax(scores, -1)
//   out[n,i] = v[n,i] * sum_j alpha[n,i,j] = v[n,i] * 1 = s[n,i] * WV[0]
// The attention cancels identically (softmax row-sum == 1): the op is an
// elementwise scale, ~1000x less work than the reference's (16384,96,96)
// softmax. Mandatory traffic: read s + write out = 12.6MB.
//
// R15: REPLICATION of R14 (e2e 6.624 = tied best; kernel dur 5.504us =
// tied best; lowest issue% of 15 configs). 15 e2e samples span 6.62-6.91
// with no config effect above noise; two prior sub-band outliers failed
// replication. This run decides whether 6.624 is claimable; the kernel is
// the final commit on kernel-dur merits either way.
//   - 256-bit ld/st.global.v8.f32 (sm_100+): halved issue count
//   - default-cached loads (s L2-resident across replays)
//   - .cs streaming stores (out evict-first, doesn't displace read set)
//   - exact tile: 384 CTAs x 256 thr x 2 f8 = 1,572,864 floats, no predicates
// ============================================================================

#define THREADS 256
#define BATCH   2

struct __align__(32) f8 { float a0,a1,a2,a3,a4,a5,a6,a7; };

__device__ __forceinline__ f8 ldg256(const f8* p) {
    f8 r;
    asm volatile(
        "ld.global.v8.f32 {%0,%1,%2,%3,%4,%5,%6,%7}, [%8];"
        : "=f"(r.a0), "=f"(r.a1), "=f"(r.a2), "=f"(r.a3),
          "=f"(r.a4), "=f"(r.a5), "=f"(r.a6), "=f"(r.a7)
        : "l"(p));
    return r;
}

__device__ __forceinline__ void stg256_cs(f8* p, const f8& v) {
    asm volatile(
        "st.global.cs.v8.f32 [%0], {%1,%2,%3,%4,%5,%6,%7,%8};"
        :: "l"(p),
           "f"(v.a0), "f"(v.a1), "f"(v.a2), "f"(v.a3),
           "f"(v.a4), "f"(v.a5), "f"(v.a6), "f"(v.a7)
        : "memory");
}

__global__ void __launch_bounds__(THREADS)
scale_v8_kernel(const f8* __restrict__ s8,
                const float* __restrict__ WV,
                f8* __restrict__ out8) {
    const float wv = __ldg(WV);
    int base = blockIdx.x * (THREADS * BATCH) + threadIdx.x;

    f8 v[BATCH];
#pragma unroll
    for (int u = 0; u < BATCH; u++)
        v[u] = ldg256(&s8[base + u * THREADS]);    // front-batched 256-bit loads
#pragma unroll
    for (int u = 0; u < BATCH; u++) {
        v[u].a0 *= wv; v[u].a1 *= wv; v[u].a2 *= wv; v[u].a3 *= wv;
        v[u].a4 *= wv; v[u].a5 *= wv; v[u].a6 *= wv; v[u].a7 *= wv;
        stg256_cs(&out8[base + u * THREADS], v[u]); // 256-bit streaming stores
    }
}

// Generic fallback (bounds-checked, grid-stride) for sizes that don't tile.
__global__ void scale_generic_kernel(const float* __restrict__ s,
                                     const float* __restrict__ WV,
                                     float* __restrict__ out, int n) {
    const float wv = WV[0];
    for (int i = blockIdx.x * blockDim.x + threadIdx.x; i < n;
         i += gridDim.x * blockDim.x)
        out[i] = s[i] * wv;
}

extern "C" void kernel_launch(void* const* d_in, const int* in_sizes, int n_in,
                              void* d_out, int out_size) {
    // metadata order: x, s, WQ, WK, WV
    const float* s  = (const float*)d_in[1];
    const float* WV = (const float*)d_in[4];
    float* out = (float*)d_out;

    int n = out_size;                               // 1,572,864 expected
    const int tile = THREADS * BATCH * 8;           // 4096 elements per CTA
    if ((n % tile) == 0 &&
        (((uintptr_t)s | (uintptr_t)out) & 31) == 0) {
        int blocks = n / tile;                      // 384
        scale_v8_kernel<<<blocks, THREADS>>>((const f8*)s, WV, (f8*)out);
    } else {
        int blocks = (n + 255) / 256;
        if (blocks > 1184) blocks = 1184;
        scale_generic_kernel<<<blocks, 256>>>(s, WV, out, n);
    }
}

// round 16
// speedup vs baseline: 1.0049x; 1.0049x over previous
#include <cuda_runtime.h>
#include <cstdint>

// ============================================================================
// CrossAttMultiplexer — analytic collapse + 256-bit memory ops (v8 family)
//
//   scores[n,i,j] = (WQ.WK)/sqrt(d) * x[n,i] * s[n,j]  (rank-1)
//   alpha = softmax(scores, -1)
//   out[n,i] = v[n,i] * sum_j alpha[n,i,j] = s[n,i] * WV[0]
// Attention cancels identically (softmax row-sum == 1). Mandatory traffic:
// read s + write out = 12.6MB.
//
// R16: the v8 config is the first REPLICATED win (R14+R15: e2e 6.624 twice,
// kernel dur 5.50/5.31us vs the 6.85-6.88 band of all 13 non-v8 configs).
// Single-variable probe within the family: BATCH=1 x 768 CTAs (double the
// CTA-level parallelism; occ was 26% and issue 4.5% at 384 CTAs, so TLP is
// the scarce resource). Exact tile: 768 x 256 x 1 f8 = 1,572,864 floats.
//   - ld.global.v8.f32 (default cache: s stays L2-resident across replays)
//   - st.global.cs.v8.f32 (streaming: out evict-first)
// ============================================================================

#define THREADS 256

struct __align__(32) f8 { float a0,a1,a2,a3,a4,a5,a6,a7; };

__device__ __forceinline__ f8 ldg256(const f8* p) {
    f8 r;
    asm volatile(
        "ld.global.v8.f32 {%0,%1,%2,%3,%4,%5,%6,%7}, [%8];"
        : "=f"(r.a0), "=f"(r.a1), "=f"(r.a2), "=f"(r.a3),
          "=f"(r.a4), "=f"(r.a5), "=f"(r.a6), "=f"(r.a7)
        : "l"(p));
    return r;
}

__device__ __forceinline__ void stg256_cs(f8* p, const f8& v) {
    asm volatile(
        "st.global.cs.v8.f32 [%0], {%1,%2,%3,%4,%5,%6,%7,%8};"
        :: "l"(p),
           "f"(v.a0), "f"(v.a1), "f"(v.a2), "f"(v.a3),
           "f"(v.a4), "f"(v.a5), "f"(v.a6), "f"(v.a7)
        : "memory");
}

__global__ void __launch_bounds__(THREADS)
scale_v8x1_kernel(const f8* __restrict__ s8,
                  const float* __restrict__ WV,
                  f8* __restrict__ out8) {
    const float wv = __ldg(WV);
    int i = blockIdx.x * THREADS + threadIdx.x;

    f8 v = ldg256(&s8[i]);
    v.a0 *= wv; v.a1 *= wv; v.a2 *= wv; v.a3 *= wv;
    v.a4 *= wv; v.a5 *= wv; v.a6 *= wv; v.a7 *= wv;
    stg256_cs(&out8[i], v);
}

// Generic fallback (bounds-checked, grid-stride) for sizes that don't tile.
__global__ void scale_generic_kernel(const float* __restrict__ s,
                                     const float* __restrict__ WV,
                                     float* __restrict__ out, int n) {
    const float wv = WV[0];
    for (int i = blockIdx.x * blockDim.x + threadIdx.x; i < n;
         i += gridDim.x * blockDim.x)
        out[i] = s[i] * wv;
}

extern "C" void kernel_launch(void* const* d_in, const int* in_sizes, int n_in,
                              void* d_out, int out_size) {
    // metadata order: x, s, WQ, WK, WV
    const float* s  = (const float*)d_in[1];
    const float* WV = (const float*)d_in[4];
    float* out = (float*)d_out;

    int n = out_size;                               // 1,572,864 expected
    const int tile = THREADS * 8;                   // 2048 elements per CTA
    if ((n % tile) == 0 &&
        (((uintptr_t)s | (uintptr_t)out) & 31) == 0) {
        int blocks = n / tile;                      // 768
        scale_v8x1_kernel<<<blocks, THREADS>>>((const f8*)s, WV, (f8*)out);
    } else {
        int blocks = (n + 255) / 256;
        if (blocks > 1184) blocks = 1184;
        scale_generic_kernel<<<blocks, 256>>>(s, WV, out, n);
    }
}